// round 1
// baseline (speedup 1.0000x reference)
#include <cuda_runtime.h>
#include <cuda_bf16.h>
#include <mma.h>

using namespace nvcuda;

// Problem constants
#define BB 2
#define SS 4096
#define DD 512
#define HH 8
#define DKK 64
#define MTOT (BB * SS)   // 8192

// ---------------------------------------------------------------------------
// Scratch (device globals; no allocation allowed)
// ---------------------------------------------------------------------------
__device__ float g_Qh[BB * HH * SS * DKK];   // [b][h][s][dk]
__device__ float g_Kh[BB * HH * SS * DKK];
__device__ float g_Vh[BB * HH * SS * DKK];
__device__ float g_AO[BB * SS * DD];         // [b][s][h*64+dk]
__device__ int   g_kidx[BB * SS];
__device__ int   g_kcnt[BB];

// ---------------------------------------------------------------------------
// Mask compaction: per batch, stable list of unmasked key positions.
// mask is (B,1,1,S) int32 in {0,1}. Softmax over -inf-masked keys is exactly
// equivalent to running attention on the compacted key set.
// ---------------------------------------------------------------------------
__global__ void compact_mask_kernel(const int* __restrict__ mask) {
    int b = blockIdx.x;
    const int* mb = mask + b * SS;
    int lane = threadIdx.x;  // 32 threads
    int base = 0;
    for (int c = 0; c < SS; c += 32) {
        int v = (mb[c + lane] != 0);
        unsigned bal = __ballot_sync(0xffffffffu, v);
        int pos = base + __popc(bal & ((1u << lane) - 1u));
        if (v) g_kidx[b * SS + pos] = c + lane;
        base += __popc(bal);
    }
    if (lane == 0) g_kcnt[b] = base;
}

// ---------------------------------------------------------------------------
// tf32 WMMA helpers
// ---------------------------------------------------------------------------
template <class Frag>
__device__ __forceinline__ void frag_to_tf32(Frag& f) {
#pragma unroll
    for (int i = 0; i < f.num_elements; i++) f.x[i] = wmma::__float_to_tf32(f.x[i]);
}

// ---------------------------------------------------------------------------
// NT GEMM: C[M,512] = X[M,512] @ W^T, W stored [out=512][in=512] row-major.
// Both A and B are K-contiguous. tf32 m16n16k8, fp32 accumulation.
// HEADOUT: write into [b][h][s][dk] layout (BN=64 tile == one full head).
// ---------------------------------------------------------------------------
template <bool HEADOUT>
__global__ __launch_bounds__(256) void gemm_tf32_kernel(
    const float* __restrict__ X, const float* __restrict__ W,
    float* __restrict__ Out)
{
    constexpr int BM = 128, BN = 64, BK = 32;
    constexpr int LDA = BK + 8;   // 40 floats -> 160B rows (16B aligned)
    constexpr int LDB = BK + 8;

    __shared__ float As[BM * LDA];
    __shared__ float Bs[BN * LDB];

    const int m0 = blockIdx.x * BM;
    const int n0 = blockIdx.y * BN;
    const int tid = threadIdx.x;
    const int w = tid >> 5;
    const int wm = w >> 1;   // 0..3 (32-row strips)
    const int wn = w & 1;    // 0..1 (32-col strips)

    wmma::fragment<wmma::accumulator, 16, 16, 8, float> c[2][2];
#pragma unroll
    for (int i = 0; i < 2; i++)
#pragma unroll
        for (int j = 0; j < 2; j++) wmma::fill_fragment(c[i][j], 0.0f);

    for (int k0 = 0; k0 < DD; k0 += BK) {
        // A tile: 128x32 floats = 1024 float4
#pragma unroll
        for (int i = tid; i < BM * BK / 4; i += 256) {
            int r = i >> 3, c4 = i & 7;
            *(float4*)&As[r * LDA + c4 * 4] =
                *(const float4*)&X[(size_t)(m0 + r) * DD + k0 + c4 * 4];
        }
        // B tile: 64x32 floats = 512 float4
#pragma unroll
        for (int i = tid; i < BN * BK / 4; i += 256) {
            int r = i >> 3, c4 = i & 7;
            *(float4*)&Bs[r * LDB + c4 * 4] =
                *(const float4*)&W[(size_t)(n0 + r) * DD + k0 + c4 * 4];
        }
        __syncthreads();

#pragma unroll
        for (int kk = 0; kk < BK; kk += 8) {
            wmma::fragment<wmma::matrix_a, 16, 16, 8, wmma::precision::tf32, wmma::row_major> a[2];
            wmma::fragment<wmma::matrix_b, 16, 16, 8, wmma::precision::tf32, wmma::col_major> bfr[2];
#pragma unroll
            for (int i = 0; i < 2; i++) {
                wmma::load_matrix_sync(a[i], &As[(wm * 32 + i * 16) * LDA + kk], LDA);
                frag_to_tf32(a[i]);
                wmma::load_matrix_sync(bfr[i], &Bs[(wn * 32 + i * 16) * LDB + kk], LDB);
                frag_to_tf32(bfr[i]);
            }
#pragma unroll
            for (int i = 0; i < 2; i++)
#pragma unroll
                for (int j = 0; j < 2; j++)
                    wmma::mma_sync(c[i][j], a[i], bfr[j], c[i][j]);
        }
        __syncthreads();
    }

    // Epilogue
#pragma unroll
    for (int i = 0; i < 2; i++) {
#pragma unroll
        for (int j = 0; j < 2; j++) {
            int mrow = m0 + wm * 32 + i * 16;
            int ncol = n0 + wn * 32 + j * 16;
            if (HEADOUT) {
                int b = mrow >> 12;        // /4096
                int s = mrow & (SS - 1);
                int h = ncol >> 6;         // /64
                int dk = ncol & 63;
                float* p = Out + (((size_t)(b * HH + h) * SS + s) * DKK) + dk;
                wmma::store_matrix_sync(p, c[i][j], DKK, wmma::mem_row_major);
            } else {
                wmma::store_matrix_sync(Out + (size_t)mrow * DD + ncol,
                                        c[i][j], DD, wmma::mem_row_major);
            }
        }
    }
}

// ---------------------------------------------------------------------------
// Flash attention over compacted keys. 64-query tile per block, 256 threads.
// Online softmax; O accumulated in shared memory (rescaled per KV tile).
// Q pre-scaled by 1/sqrt(64)=0.125 at load.
// ---------------------------------------------------------------------------
#define LDP 72   // 288B rows: 16B aligned, multiple of 8 floats

__global__ __launch_bounds__(256) void flash_kernel(
    const float* __restrict__ Qh, const float* __restrict__ Kh,
    const float* __restrict__ Vh, const int* __restrict__ kidx,
    const int* __restrict__ kcnt, float* __restrict__ AO)
{
    extern __shared__ float sm[];
    float* Qs  = sm;                 // 64 x LDP   (q, d)
    float* Ks  = Qs  + 64 * LDP;     // 64 x LDP   (key, d)
    float* Vst = Ks  + 64 * LDP;     // 64 x LDP   (d, key)  -- transposed
    float* Ss  = Vst + 64 * LDP;     // 64 x LDP   (q, key) scores then P
    float* Os  = Ss  + 64 * LDP;     // 64 x LDP   (q, d) running output
    float* m_sm = Os + 64 * LDP;     // 64
    float* l_sm = m_sm + 64;         // 64

    const int q0 = blockIdx.x * 64;
    const int h = blockIdx.y;
    const int b = blockIdx.z;
    const int tid = threadIdx.x;
    const int w = tid >> 5;
    const int L = kcnt[b];
    const int* idx = kidx + b * SS;
    const size_t headbase = (size_t)(b * HH + h) * SS * DKK;

    // Load Q tile, scaled
#pragma unroll
    for (int i = tid; i < 64 * 16; i += 256) {
        int r = i >> 4, c4 = i & 15;
        float4 v = *(const float4*)&Qh[headbase + (size_t)(q0 + r) * DKK + c4 * 4];
        v.x *= 0.125f; v.y *= 0.125f; v.z *= 0.125f; v.w *= 0.125f;
        *(float4*)&Qs[r * LDP + c4 * 4] = v;
    }
    // Init O, m, l
#pragma unroll
    for (int i = tid; i < 64 * 16; i += 256) {
        int r = i >> 4, c4 = i & 15;
        *(float4*)&Os[r * LDP + c4 * 4] = make_float4(0.f, 0.f, 0.f, 0.f);
    }
    if (tid < 64) { m_sm[tid] = -1e30f; l_sm[tid] = 0.f; }
    __syncthreads();

    const int nkt = (L + 63) >> 6;
    for (int kt = 0; kt < nkt; kt++) {
        const int kbase = kt * 64;
        // Gather K tile (row-major) and V tile (transposed)
#pragma unroll
        for (int i = tid; i < 64 * 16; i += 256) {
            int j = i >> 4, c4 = i & 15;
            int gk = kbase + j;
            float4 kv, vv;
            if (gk < L) {
                int row = idx[gk];
                kv = *(const float4*)&Kh[headbase + (size_t)row * DKK + c4 * 4];
                vv = *(const float4*)&Vh[headbase + (size_t)row * DKK + c4 * 4];
            } else {
                kv = make_float4(0.f, 0.f, 0.f, 0.f);
                vv = kv;
            }
            *(float4*)&Ks[j * LDP + c4 * 4] = kv;
            int d = c4 * 4;
            Vst[(d + 0) * LDP + j] = vv.x;
            Vst[(d + 1) * LDP + j] = vv.y;
            Vst[(d + 2) * LDP + j] = vv.z;
            Vst[(d + 3) * LDP + j] = vv.w;
        }
        __syncthreads();

        // S = Qs (64x64) @ Ks^T (64x64): 16 tiles of 16x16, 2 per warp
        for (int t = w; t < 16; t += 8) {
            int qt = t >> 2, kt2 = t & 3;
            wmma::fragment<wmma::accumulator, 16, 16, 8, float> cfr;
            wmma::fill_fragment(cfr, 0.0f);
#pragma unroll
            for (int kk = 0; kk < 64; kk += 8) {
                wmma::fragment<wmma::matrix_a, 16, 16, 8, wmma::precision::tf32, wmma::row_major> a;
                wmma::fragment<wmma::matrix_b, 16, 16, 8, wmma::precision::tf32, wmma::col_major> bf;
                wmma::load_matrix_sync(a, &Qs[(qt * 16) * LDP + kk], LDP);
                frag_to_tf32(a);
                wmma::load_matrix_sync(bf, &Ks[(kt2 * 16) * LDP + kk], LDP);
                frag_to_tf32(bf);
                wmma::mma_sync(cfr, a, bf, cfr);
            }
            wmma::store_matrix_sync(&Ss[(qt * 16) * LDP + kt2 * 16], cfr, LDP,
                                    wmma::mem_row_major);
        }
        __syncthreads();

        // Online softmax: 4 threads per query row (16 cols each)
        {
            int r = tid >> 2, q4 = tid & 3;
            float sv[16];
            float mx = -1e30f;
#pragma unroll
            for (int jj = 0; jj < 16; jj++) {
                int cc = q4 * 16 + jj;
                float s = (kbase + cc < L) ? Ss[r * LDP + cc] : -1e30f;
                sv[jj] = s;
                mx = fmaxf(mx, s);
            }
            mx = fmaxf(mx, __shfl_xor_sync(0xffffffffu, mx, 1));
            mx = fmaxf(mx, __shfl_xor_sync(0xffffffffu, mx, 2));
            float mprev = m_sm[r];
            float mnew = fmaxf(mprev, mx);
            float psum = 0.f;
#pragma unroll
            for (int jj = 0; jj < 16; jj++) {
                float p = __expf(sv[jj] - mnew);
                Ss[r * LDP + q4 * 16 + jj] = p;
                psum += p;
            }
            psum += __shfl_xor_sync(0xffffffffu, psum, 1);
            psum += __shfl_xor_sync(0xffffffffu, psum, 2);
            float alpha = __expf(mprev - mnew);
            float lnew = l_sm[r] * alpha + psum;
            // Rescale running O
#pragma unroll
            for (int jj = 0; jj < 16; jj++)
                Os[r * LDP + q4 * 16 + jj] *= alpha;
            if (q4 == 0) { m_sm[r] = mnew; l_sm[r] = lnew; }
        }
        __syncthreads();

        // O += P (64x64) @ V (64x64): 16 tiles of 16x16, 2 per warp
        for (int t = w; t < 16; t += 8) {
            int qt = t >> 2, dt = t & 3;
            wmma::fragment<wmma::accumulator, 16, 16, 8, float> cfr;
            wmma::load_matrix_sync(cfr, &Os[(qt * 16) * LDP + dt * 16], LDP,
                                   wmma::mem_row_major);
#pragma unroll
            for (int kk = 0; kk < 64; kk += 8) {
                wmma::fragment<wmma::matrix_a, 16, 16, 8, wmma::precision::tf32, wmma::row_major> a;
                wmma::fragment<wmma::matrix_b, 16, 16, 8, wmma::precision::tf32, wmma::col_major> bf;
                wmma::load_matrix_sync(a, &Ss[(qt * 16) * LDP + kk], LDP);
                frag_to_tf32(a);
                wmma::load_matrix_sync(bf, &Vst[(dt * 16) * LDP + kk], LDP);
                frag_to_tf32(bf);
                wmma::mma_sync(cfr, a, bf, cfr);
            }
            wmma::store_matrix_sync(&Os[(qt * 16) * LDP + dt * 16], cfr, LDP,
                                    wmma::mem_row_major);
        }
        __syncthreads();
    }

    // Epilogue: normalize by l (0 rows if all keys masked -> matches nan_to_num)
    {
        int r = tid >> 2, q4 = tid & 3;
        float l = l_sm[r];
        float inv = (l > 0.f) ? (1.f / l) : 0.f;
#pragma unroll
        for (int jj = 0; jj < 16; jj++) {
            int dkc = q4 * 16 + jj;
            AO[((size_t)b * SS + q0 + r) * DD + h * DKK + dkc] =
                Os[r * LDP + dkc] * inv;
        }
    }
}

// ---------------------------------------------------------------------------
// Launch
// ---------------------------------------------------------------------------
extern "C" void kernel_launch(void* const* d_in, const int* in_sizes, int n_in,
                              void* d_out, int out_size)
{
    const float* q    = (const float*)d_in[0];
    const float* k    = (const float*)d_in[1];
    const float* v    = (const float*)d_in[2];
    const int*   mask = (const int*)d_in[3];
    const float* Wq   = (const float*)d_in[4];
    const float* Wk   = (const float*)d_in[5];
    const float* Wv   = (const float*)d_in[6];
    const float* Wo   = (const float*)d_in[7];
    float* out = (float*)d_out;

    float *Qh, *Kh, *Vh, *AO;
    int *kidx, *kcnt;
    cudaGetSymbolAddress((void**)&Qh, g_Qh);
    cudaGetSymbolAddress((void**)&Kh, g_Kh);
    cudaGetSymbolAddress((void**)&Vh, g_Vh);
    cudaGetSymbolAddress((void**)&AO, g_AO);
    cudaGetSymbolAddress((void**)&kidx, g_kidx);
    cudaGetSymbolAddress((void**)&kcnt, g_kcnt);
    (void)kidx; (void)kcnt;  // kernels reference the globals directly

    const int smem = (5 * 64 * LDP + 128) * (int)sizeof(float);
    cudaFuncSetAttribute(flash_kernel,
                         cudaFuncAttributeMaxDynamicSharedMemorySize, smem);

    compact_mask_kernel<<<BB, 32>>>(mask);

    dim3 gproj(MTOT / 128, DD / 64);
    gemm_tf32_kernel<true><<<gproj, 256>>>(q, Wq, Qh);
    gemm_tf32_kernel<true><<<gproj, 256>>>(k, Wk, Kh);
    gemm_tf32_kernel<true><<<gproj, 256>>>(v, Wv, Vh);

    dim3 gflash(SS / 64, HH, BB);
    flash_kernel<<<gflash, 256, smem>>>(Qh, Kh, Vh,
                                        (const int*)kidx, (const int*)kcnt, AO);

    gemm_tf32_kernel<false><<<gproj, 256>>>(AO, Wo, out);
}

// round 4
// speedup vs baseline: 2.5152x; 2.5152x over previous
#include <cuda_runtime.h>
#include <cuda_bf16.h>
#include <mma.h>
#include <cstdint>

using namespace nvcuda;

// Problem constants
#define BB 2
#define SS 4096
#define DD 512
#define HH 8
#define DKK 64
#define MTOT (BB * SS)   // 8192

// scale folded into Q projection: 1/sqrt(64) * log2(e)
#define QSCALE 0.18033688011112042f

// ---------------------------------------------------------------------------
// Scratch (device globals; no allocation allowed)
// ---------------------------------------------------------------------------
__device__ float g_Qh[BB * HH * SS * DKK];   // [b][h][s][dk]
__device__ float g_Kh[BB * HH * SS * DKK];
__device__ float g_Vh[BB * HH * SS * DKK];
__device__ float g_AO[BB * SS * DD];         // [b][s][h*64+dk]
__device__ int   g_kidx[BB * SS];
__device__ int   g_kcnt[BB];

// ---------------------------------------------------------------------------
// Mask compaction (stable, deterministic)
// ---------------------------------------------------------------------------
__global__ void compact_mask_kernel(const int* __restrict__ mask) {
    int b = blockIdx.x;
    const int* mb = mask + b * SS;
    int lane = threadIdx.x;  // 32 threads
    int base = 0;
    for (int c = 0; c < SS; c += 32) {
        int v = (mb[c + lane] != 0);
        unsigned bal = __ballot_sync(0xffffffffu, v);
        int pos = base + __popc(bal & ((1u << lane) - 1u));
        if (v) g_kidx[b * SS + pos] = c + lane;
        base += __popc(bal);
    }
    if (lane == 0) g_kcnt[b] = base;
}

// ---------------------------------------------------------------------------
// Helpers
// ---------------------------------------------------------------------------
__device__ __forceinline__ float f2tf(float x) {
    uint32_t u;
    asm("cvt.rna.tf32.f32 %0, %1;" : "=r"(u) : "f"(x));
    return __uint_as_float(u);
}

__device__ __forceinline__ void mma_tf32(float* c, const uint32_t* a,
                                         uint32_t b0, uint32_t b1) {
    asm volatile(
        "mma.sync.aligned.m16n8k8.row.col.f32.tf32.tf32.f32 "
        "{%0,%1,%2,%3}, {%4,%5,%6,%7}, {%8,%9}, {%0,%1,%2,%3};\n"
        : "+f"(c[0]), "+f"(c[1]), "+f"(c[2]), "+f"(c[3])
        : "r"(a[0]), "r"(a[1]), "r"(a[2]), "r"(a[3]), "r"(b0), "r"(b1));
}

template <class Frag>
__device__ __forceinline__ void frag_to_tf32(Frag& f) {
#pragma unroll
    for (int i = 0; i < f.num_elements; i++) f.x[i] = wmma::__float_to_tf32(f.x[i]);
}

// ---------------------------------------------------------------------------
// NT GEMM: C[M,512] = X[M,512] @ W^T (tf32 WMMA). HEADOUT -> [b][h][s][dk].
// SCALE folds softmax scale into the Q projection.
// ---------------------------------------------------------------------------
template <bool HEADOUT, bool SCALE>
__global__ __launch_bounds__(256) void gemm_tf32_kernel(
    const float* __restrict__ X, const float* __restrict__ W,
    float* __restrict__ Out)
{
    constexpr int BM = 128, BN = 64, BK = 32;
    constexpr int LDA = BK + 8;
    constexpr int LDB = BK + 8;

    __shared__ float As[BM * LDA];
    __shared__ float Bs[BN * LDB];

    const int m0 = blockIdx.x * BM;
    const int n0 = blockIdx.y * BN;
    const int tid = threadIdx.x;
    const int w = tid >> 5;
    const int wm = w >> 1;
    const int wn = w & 1;

    wmma::fragment<wmma::accumulator, 16, 16, 8, float> c[2][2];
#pragma unroll
    for (int i = 0; i < 2; i++)
#pragma unroll
        for (int j = 0; j < 2; j++) wmma::fill_fragment(c[i][j], 0.0f);

    for (int k0 = 0; k0 < DD; k0 += BK) {
#pragma unroll
        for (int i = tid; i < BM * BK / 4; i += 256) {
            int r = i >> 3, c4 = i & 7;
            *(float4*)&As[r * LDA + c4 * 4] =
                *(const float4*)&X[(size_t)(m0 + r) * DD + k0 + c4 * 4];
        }
#pragma unroll
        for (int i = tid; i < BN * BK / 4; i += 256) {
            int r = i >> 3, c4 = i & 7;
            *(float4*)&Bs[r * LDB + c4 * 4] =
                *(const float4*)&W[(size_t)(n0 + r) * DD + k0 + c4 * 4];
        }
        __syncthreads();

#pragma unroll
        for (int kk = 0; kk < BK; kk += 8) {
            wmma::fragment<wmma::matrix_a, 16, 16, 8, wmma::precision::tf32, wmma::row_major> a[2];
            wmma::fragment<wmma::matrix_b, 16, 16, 8, wmma::precision::tf32, wmma::col_major> bfr[2];
#pragma unroll
            for (int i = 0; i < 2; i++) {
                wmma::load_matrix_sync(a[i], &As[(wm * 32 + i * 16) * LDA + kk], LDA);
                frag_to_tf32(a[i]);
                wmma::load_matrix_sync(bfr[i], &Bs[(wn * 32 + i * 16) * LDB + kk], LDB);
                frag_to_tf32(bfr[i]);
            }
#pragma unroll
            for (int i = 0; i < 2; i++)
#pragma unroll
                for (int j = 0; j < 2; j++)
                    wmma::mma_sync(c[i][j], a[i], bfr[j], c[i][j]);
        }
        __syncthreads();
    }

#pragma unroll
    for (int i = 0; i < 2; i++) {
#pragma unroll
        for (int j = 0; j < 2; j++) {
            if (SCALE) {
#pragma unroll
                for (int e = 0; e < c[i][j].num_elements; e++)
                    c[i][j].x[e] *= QSCALE;
            }
            int mrow = m0 + wm * 32 + i * 16;
            int ncol = n0 + wn * 32 + j * 16;
            if (HEADOUT) {
                int b = mrow >> 12;
                int s = mrow & (SS - 1);
                int h = ncol >> 6;
                int dk = ncol & 63;
                float* p = Out + (((size_t)(b * HH + h) * SS + s) * DKK) + dk;
                wmma::store_matrix_sync(p, c[i][j], DKK, wmma::mem_row_major);
            } else {
                wmma::store_matrix_sync(Out + (size_t)mrow * DD + ncol,
                                        c[i][j], DD, wmma::mem_row_major);
            }
        }
    }
}

// ---------------------------------------------------------------------------
// Flash attention v2: register-resident, mma.m16n8k8 tf32.
// Block = 128 queries, 8 warps (16 queries each). KV tile = 64 keys.
// Softmax in log2 domain (scale pre-folded into Q).
// ---------------------------------------------------------------------------
#define LDK 68   // K tile stride (floats): conflict-free for (4g+t) pattern
#define LDV 72   // V tile stride: conflict-free for (8t+8nt+g) pattern
#define LDQ 68   // Q staging / per-warp P stride

__global__ __launch_bounds__(256) void flash2_kernel(
    const float* __restrict__ Qh, const float* __restrict__ Kh,
    const float* __restrict__ Vh, const int* __restrict__ kidx,
    const int* __restrict__ kcnt, float* __restrict__ AO)
{
    extern __shared__ float sm[];
    float* Ksm = sm;                    // 64 * LDK
    float* Vsm = Ksm + 64 * LDK;        // 64 * LDV
    float* Psm = Vsm + 64 * LDV;        // 128 * LDQ (Q staging, then per-warp P)

    const int q0 = blockIdx.x * 128;
    const int h  = blockIdx.y;
    const int b  = blockIdx.z;
    const int tid  = threadIdx.x;
    const int lane = tid & 31;
    const int w    = tid >> 5;
    const int g    = lane >> 2;   // group id (row within 8)
    const int t    = lane & 3;    // thread in group
    const int L = kcnt[b];
    const int* idx = kidx + (size_t)b * SS;
    const size_t headbase = (size_t)(b * HH + h) * SS * DKK;
    float* Pw = Psm + w * 16 * LDQ;   // this warp's 16xLDQ region

    // ---- Stage Q tile (pre-scaled, convert to tf32 once) ----
#pragma unroll 2
    for (int i = tid; i < 128 * 16; i += 256) {
        int r = i >> 4, c4 = i & 15;
        float4 v = *(const float4*)&Qh[headbase + (size_t)(q0 + r) * DKK + c4 * 4];
        v.x = f2tf(v.x); v.y = f2tf(v.y); v.z = f2tf(v.z); v.w = f2tf(v.w);
        *(float4*)&Psm[r * LDQ + c4 * 4] = v;
    }
    __syncthreads();

    // ---- Load Q fragments (A layout, m16n8k8): 8 k-steps ----
    uint32_t qa[8][4];
#pragma unroll
    for (int ks = 0; ks < 8; ks++) {
        qa[ks][0] = __float_as_uint(Pw[g * LDQ + ks * 8 + t]);
        qa[ks][1] = __float_as_uint(Pw[(g + 8) * LDQ + ks * 8 + t]);
        qa[ks][2] = __float_as_uint(Pw[g * LDQ + ks * 8 + t + 4]);
        qa[ks][3] = __float_as_uint(Pw[(g + 8) * LDQ + ks * 8 + t + 4]);
    }
    // (Psm reuse as P is warp-private from here on; no block sync needed for it)

    float oacc[8][4];
#pragma unroll
    for (int nt = 0; nt < 8; nt++)
#pragma unroll
        for (int e = 0; e < 4; e++) oacc[nt][e] = 0.0f;
    float m0 = -1e30f, m1 = -1e30f, l0 = 0.0f, l1 = 0.0f;

    const int nkt = (L + 63) >> 6;
    for (int kt = 0; kt < nkt; kt++) {
        const int kbase = kt * 64;
        __syncthreads();   // previous tile's compute done before overwrite

        // ---- Gather K/V tile (zero-fill tail), convert to tf32 ----
#pragma unroll 2
        for (int i = tid; i < 64 * 16; i += 256) {
            int j = i >> 4, c4 = i & 15;
            int gk = kbase + j;
            float4 kv = make_float4(0.f, 0.f, 0.f, 0.f);
            float4 vv = kv;
            if (gk < L) {
                int row = idx[gk];
                kv = *(const float4*)&Kh[headbase + (size_t)row * DKK + c4 * 4];
                vv = *(const float4*)&Vh[headbase + (size_t)row * DKK + c4 * 4];
            }
            kv.x = f2tf(kv.x); kv.y = f2tf(kv.y); kv.z = f2tf(kv.z); kv.w = f2tf(kv.w);
            vv.x = f2tf(vv.x); vv.y = f2tf(vv.y); vv.z = f2tf(vv.z); vv.w = f2tf(vv.w);
            *(float4*)&Ksm[j * LDK + c4 * 4] = kv;
            *(float4*)&Vsm[j * LDV + c4 * 4] = vv;
        }
        __syncthreads();

        // ---- S = Q K^T : 8 accumulator tiles (16x8 each) ----
        float sacc[8][4];
#pragma unroll
        for (int nt = 0; nt < 8; nt++)
#pragma unroll
            for (int e = 0; e < 4; e++) sacc[nt][e] = 0.0f;

#pragma unroll
        for (int ks = 0; ks < 8; ks++) {
#pragma unroll
            for (int nt = 0; nt < 8; nt++) {
                uint32_t b0 = __float_as_uint(Ksm[(nt * 8 + g) * LDK + ks * 8 + t]);
                uint32_t b1 = __float_as_uint(Ksm[(nt * 8 + g) * LDK + ks * 8 + t + 4]);
                mma_tf32(sacc[nt], qa[ks], b0, b1);
            }
        }

        // ---- mask tail columns ----
        if (kbase + 64 > L) {
#pragma unroll
            for (int nt = 0; nt < 8; nt++) {
                int c0 = kbase + nt * 8 + 2 * t;
                if (c0 >= L)     { sacc[nt][0] = -1e30f; sacc[nt][2] = -1e30f; }
                if (c0 + 1 >= L) { sacc[nt][1] = -1e30f; sacc[nt][3] = -1e30f; }
            }
        }

        // ---- online softmax (log2 domain) ----
        float tm0 = -1e30f, tm1 = -1e30f;
#pragma unroll
        for (int nt = 0; nt < 8; nt++) {
            tm0 = fmaxf(tm0, fmaxf(sacc[nt][0], sacc[nt][1]));
            tm1 = fmaxf(tm1, fmaxf(sacc[nt][2], sacc[nt][3]));
        }
        tm0 = fmaxf(tm0, __shfl_xor_sync(0xffffffffu, tm0, 1));
        tm0 = fmaxf(tm0, __shfl_xor_sync(0xffffffffu, tm0, 2));
        tm1 = fmaxf(tm1, __shfl_xor_sync(0xffffffffu, tm1, 1));
        tm1 = fmaxf(tm1, __shfl_xor_sync(0xffffffffu, tm1, 2));

        float mn0 = fmaxf(m0, tm0), mn1 = fmaxf(m1, tm1);
        float al0 = exp2f(m0 - mn0), al1 = exp2f(m1 - mn1);
        float ps0 = 0.f, ps1 = 0.f;
#pragma unroll
        for (int nt = 0; nt < 8; nt++) {
            sacc[nt][0] = exp2f(sacc[nt][0] - mn0);
            sacc[nt][1] = exp2f(sacc[nt][1] - mn0);
            sacc[nt][2] = exp2f(sacc[nt][2] - mn1);
            sacc[nt][3] = exp2f(sacc[nt][3] - mn1);
            ps0 += sacc[nt][0] + sacc[nt][1];
            ps1 += sacc[nt][2] + sacc[nt][3];
        }
        ps0 += __shfl_xor_sync(0xffffffffu, ps0, 1);
        ps0 += __shfl_xor_sync(0xffffffffu, ps0, 2);
        ps1 += __shfl_xor_sync(0xffffffffu, ps1, 1);
        ps1 += __shfl_xor_sync(0xffffffffu, ps1, 2);
        l0 = l0 * al0 + ps0;  m0 = mn0;
        l1 = l1 * al1 + ps1;  m1 = mn1;

#pragma unroll
        for (int nt = 0; nt < 8; nt++) {
            oacc[nt][0] *= al0; oacc[nt][1] *= al0;
            oacc[nt][2] *= al1; oacc[nt][3] *= al1;
        }

        // ---- P C-layout -> warp-private shared (as tf32) ----
#pragma unroll
        for (int nt = 0; nt < 8; nt++) {
            float2 p01 = make_float2(f2tf(sacc[nt][0]), f2tf(sacc[nt][1]));
            float2 p23 = make_float2(f2tf(sacc[nt][2]), f2tf(sacc[nt][3]));
            *(float2*)&Pw[g * LDQ + nt * 8 + 2 * t] = p01;
            *(float2*)&Pw[(g + 8) * LDQ + nt * 8 + 2 * t] = p23;
        }
        __syncwarp();

        // ---- O += P V : A = P (k=keys), B = V ----
#pragma unroll
        for (int ks = 0; ks < 8; ks++) {
            uint32_t pa[4];
            pa[0] = __float_as_uint(Pw[g * LDQ + ks * 8 + t]);
            pa[1] = __float_as_uint(Pw[(g + 8) * LDQ + ks * 8 + t]);
            pa[2] = __float_as_uint(Pw[g * LDQ + ks * 8 + t + 4]);
            pa[3] = __float_as_uint(Pw[(g + 8) * LDQ + ks * 8 + t + 4]);
#pragma unroll
            for (int nt = 0; nt < 8; nt++) {
                uint32_t b0 = __float_as_uint(Vsm[(ks * 8 + t) * LDV + nt * 8 + g]);
                uint32_t b1 = __float_as_uint(Vsm[(ks * 8 + t + 4) * LDV + nt * 8 + g]);
                mma_tf32(oacc[nt], pa, b0, b1);
            }
        }
        __syncwarp();   // P reads done before next iteration's P writes
    }

    // ---- Epilogue: normalize, store to AO [b][s][h*64+dk] ----
    float inv0 = (l0 > 0.f) ? (1.0f / l0) : 0.0f;
    float inv1 = (l1 > 0.f) ? (1.0f / l1) : 0.0f;
    int qr0 = q0 + w * 16 + g;
    size_t base0 = ((size_t)b * SS + qr0) * DD + h * DKK;
    size_t base1 = base0 + (size_t)8 * DD;
#pragma unroll
    for (int nt = 0; nt < 8; nt++) {
        *(float2*)&AO[base0 + nt * 8 + 2 * t] =
            make_float2(oacc[nt][0] * inv0, oacc[nt][1] * inv0);
        *(float2*)&AO[base1 + nt * 8 + 2 * t] =
            make_float2(oacc[nt][2] * inv1, oacc[nt][3] * inv1);
    }
}

// ---------------------------------------------------------------------------
// Launch
// ---------------------------------------------------------------------------
extern "C" void kernel_launch(void* const* d_in, const int* in_sizes, int n_in,
                              void* d_out, int out_size)
{
    const float* q    = (const float*)d_in[0];
    const float* k    = (const float*)d_in[1];
    const float* v    = (const float*)d_in[2];
    const int*   mask = (const int*)d_in[3];
    const float* Wq   = (const float*)d_in[4];
    const float* Wk   = (const float*)d_in[5];
    const float* Wv   = (const float*)d_in[6];
    const float* Wo   = (const float*)d_in[7];
    float* out = (float*)d_out;

    float *Qh, *Kh, *Vh, *AO;
    int *kidx, *kcnt;
    cudaGetSymbolAddress((void**)&Qh, g_Qh);
    cudaGetSymbolAddress((void**)&Kh, g_Kh);
    cudaGetSymbolAddress((void**)&Vh, g_Vh);
    cudaGetSymbolAddress((void**)&AO, g_AO);
    cudaGetSymbolAddress((void**)&kidx, g_kidx);
    cudaGetSymbolAddress((void**)&kcnt, g_kcnt);

    const int smem = (64 * LDK + 64 * LDV + 128 * LDQ) * (int)sizeof(float);
    cudaFuncSetAttribute(flash2_kernel,
                         cudaFuncAttributeMaxDynamicSharedMemorySize, smem);

    compact_mask_kernel<<<BB, 32>>>(mask);

    dim3 gproj(MTOT / 128, DD / 64);
    gemm_tf32_kernel<true, true ><<<gproj, 256>>>(q, Wq, Qh);
    gemm_tf32_kernel<true, false><<<gproj, 256>>>(k, Wk, Kh);
    gemm_tf32_kernel<true, false><<<gproj, 256>>>(v, Wv, Vh);

    dim3 gflash(SS / 128, HH, BB);
    flash2_kernel<<<gflash, 256, smem>>>(Qh, Kh, Vh,
                                         (const int*)kidx, (const int*)kcnt, AO);

    gemm_tf32_kernel<false, false><<<gproj, 256>>>(AO, Wo, out);
}

// round 5
// speedup vs baseline: 3.2354x; 1.2864x over previous
#include <cuda_runtime.h>
#include <cuda_bf16.h>
#include <mma.h>
#include <cstdint>

// Problem constants
#define BB 2
#define SS 4096
#define DD 512
#define HH 8
#define DKK 64
#define MTOT (BB * SS)   // 8192

// scale folded into Q projection: 1/sqrt(64) * log2(e)
#define QSCALE 0.18033688011112042f

// ---------------------------------------------------------------------------
// Scratch (device globals; no allocation allowed)
// ---------------------------------------------------------------------------
__device__ float g_Qh[BB * HH * SS * DKK];   // [b][h][s][dk]
__device__ float g_Kh[BB * HH * SS * DKK];
__device__ float g_Vh[BB * HH * SS * DKK];
__device__ float g_AO[BB * SS * DD];         // [b][s][h*64+dk]
__device__ int   g_kidx[BB * SS];
__device__ int   g_kcnt[BB];

// ---------------------------------------------------------------------------
// Mask compaction (stable, deterministic)
// ---------------------------------------------------------------------------
__global__ void compact_mask_kernel(const int* __restrict__ mask) {
    int b = blockIdx.x;
    const int* mb = mask + b * SS;
    int lane = threadIdx.x;  // 32 threads
    int base = 0;
    for (int c = 0; c < SS; c += 32) {
        int v = (mb[c + lane] != 0);
        unsigned bal = __ballot_sync(0xffffffffu, v);
        int pos = base + __popc(bal & ((1u << lane) - 1u));
        if (v) g_kidx[b * SS + pos] = c + lane;
        base += __popc(bal);
    }
    if (lane == 0) g_kcnt[b] = base;
}

// ---------------------------------------------------------------------------
// Helpers
// ---------------------------------------------------------------------------
__device__ __forceinline__ float f2tf(float x) {
    uint32_t u;
    asm("cvt.rna.tf32.f32 %0, %1;" : "=r"(u) : "f"(x));
    return __uint_as_float(u);
}

__device__ __forceinline__ uint32_t f2tfu(float x) {
    uint32_t u;
    asm("cvt.rna.tf32.f32 %0, %1;" : "=r"(u) : "f"(x));
    return u;
}

__device__ __forceinline__ void mma_tf32(float* c, const uint32_t* a,
                                         uint32_t b0, uint32_t b1) {
    asm volatile(
        "mma.sync.aligned.m16n8k8.row.col.f32.tf32.tf32.f32 "
        "{%0,%1,%2,%3}, {%4,%5,%6,%7}, {%8,%9}, {%0,%1,%2,%3};\n"
        : "+f"(c[0]), "+f"(c[1]), "+f"(c[2]), "+f"(c[3])
        : "r"(a[0]), "r"(a[1]), "r"(a[2]), "r"(a[3]), "r"(b0), "r"(b1));
}

__device__ __forceinline__ void cp_async16(float* smem_dst, const float* gsrc) {
    unsigned sa = (unsigned)__cvta_generic_to_shared(smem_dst);
    asm volatile("cp.async.cg.shared.global [%0], [%1], 16;" :: "r"(sa), "l"(gsrc));
}

// ---------------------------------------------------------------------------
// GEMM v2: C[M,512] = X[M,512] @ W^T, raw mma.m16n8k8 tf32,
// cp.async double-buffered. BM=128, BN=128, BK=32, 256 threads (8 warps),
// warp tile 64x32 (wm in {0,1}, wn in {0..3}).
// HEADOUT -> [b][h][s][dk]; SCALE folds softmax scale into Q projection.
// ---------------------------------------------------------------------------
#define G_BM 128
#define G_BN 128
#define G_BK 32
#define G_LDA 36    // bank pattern (4g+t): conflict-free
#define G_STAGE (G_BM * G_LDA + G_BN * G_LDA)
#define G_NIT (DD / G_BK)   // 16

template <bool HEADOUT, bool SCALE>
__global__ __launch_bounds__(256, 2) void gemm2_kernel(
    const float* __restrict__ X, const float* __restrict__ W,
    float* __restrict__ Out)
{
    extern __shared__ float smem[];

    const int m0 = blockIdx.x * G_BM;
    const int n0 = blockIdx.y * G_BN;
    const int tid  = threadIdx.x;
    const int lane = tid & 31;
    const int w    = tid >> 5;
    const int g    = lane >> 2;
    const int t    = lane & 3;
    const int wm   = w >> 2;   // 0..1 : 64-row strip
    const int wn   = w & 3;    // 0..3 : 32-col strip

    float acc[4][4][4];
#pragma unroll
    for (int mt = 0; mt < 4; mt++)
#pragma unroll
        for (int nt = 0; nt < 4; nt++)
#pragma unroll
            for (int e = 0; e < 4; e++) acc[mt][nt][e] = 0.0f;

    // ---- stage loader: 128x32 A + 128x32 B, 16B cp.async, coalesced ----
    auto load_stage = [&](int s, int k0) {
        float* As = smem + s * G_STAGE;
        float* Bs = As + G_BM * G_LDA;
#pragma unroll
        for (int j = 0; j < 4; j++) {
            int idx = tid * 4 + j;         // 0..1023
            int r = idx >> 3, seg = idx & 7;
            cp_async16(&As[r * G_LDA + seg * 4],
                       &X[(size_t)(m0 + r) * DD + k0 + seg * 4]);
            cp_async16(&Bs[r * G_LDA + seg * 4],
                       &W[(size_t)(n0 + r) * DD + k0 + seg * 4]);
        }
        asm volatile("cp.async.commit_group;" ::: "memory");
    };

    load_stage(0, 0);

    for (int it = 0; it < G_NIT; it++) {
        asm volatile("cp.async.wait_group 0;" ::: "memory");
        __syncthreads();
        if (it + 1 < G_NIT) load_stage((it + 1) & 1, (it + 1) * G_BK);

        const float* As = smem + (it & 1) * G_STAGE;
        const float* Bs = As + G_BM * G_LDA;

#pragma unroll
        for (int ks = 0; ks < 4; ks++) {
            uint32_t af[4][4];
            uint32_t bf[4][2];
#pragma unroll
            for (int mt = 0; mt < 4; mt++) {
                int r = wm * 64 + mt * 16;
                af[mt][0] = f2tfu(As[(r + g)     * G_LDA + ks * 8 + t]);
                af[mt][1] = f2tfu(As[(r + g + 8) * G_LDA + ks * 8 + t]);
                af[mt][2] = f2tfu(As[(r + g)     * G_LDA + ks * 8 + t + 4]);
                af[mt][3] = f2tfu(As[(r + g + 8) * G_LDA + ks * 8 + t + 4]);
            }
#pragma unroll
            for (int nt = 0; nt < 4; nt++) {
                int c = wn * 32 + nt * 8;
                bf[nt][0] = f2tfu(Bs[(c + g) * G_LDA + ks * 8 + t]);
                bf[nt][1] = f2tfu(Bs[(c + g) * G_LDA + ks * 8 + t + 4]);
            }
#pragma unroll
            for (int mt = 0; mt < 4; mt++)
#pragma unroll
                for (int nt = 0; nt < 4; nt++)
                    mma_tf32(acc[mt][nt], af[mt], bf[nt][0], bf[nt][1]);
        }
        __syncthreads();
    }

    // ---- epilogue ----
#pragma unroll
    for (int mt = 0; mt < 4; mt++) {
#pragma unroll
        for (int nt = 0; nt < 4; nt++) {
            float* a = acc[mt][nt];
            if (SCALE) {
                a[0] *= QSCALE; a[1] *= QSCALE; a[2] *= QSCALE; a[3] *= QSCALE;
            }
            int row0 = m0 + wm * 64 + mt * 16 + g;
            int col  = n0 + wn * 32 + nt * 8 + 2 * t;
            if (HEADOUT) {
                int h  = col >> 6;
                int dk = col & 63;
                int b0_ = row0 >> 12;
                int s0 = row0 & (SS - 1);
                float* p0 = Out + (((size_t)(b0_ * HH + h) * SS + s0) * DKK) + dk;
                *(float2*)p0 = make_float2(a[0], a[1]);
                int row1 = row0 + 8;
                int b1_ = row1 >> 12;
                int s1 = row1 & (SS - 1);
                float* p1 = Out + (((size_t)(b1_ * HH + h) * SS + s1) * DKK) + dk;
                *(float2*)p1 = make_float2(a[2], a[3]);
            } else {
                *(float2*)&Out[(size_t)row0 * DD + col] = make_float2(a[0], a[1]);
                *(float2*)&Out[(size_t)(row0 + 8) * DD + col] = make_float2(a[2], a[3]);
            }
        }
    }
}

// ---------------------------------------------------------------------------
// Flash attention v2: register-resident, mma.m16n8k8 tf32. (unchanged; at
// legacy-HMMA ceiling ~123 TF/s)
// ---------------------------------------------------------------------------
#define LDK 68   // K tile stride (floats): conflict-free for (4g+t) pattern
#define LDV 72   // V tile stride: conflict-free for (8t+8nt+g) pattern
#define LDQ 68   // Q staging / per-warp P stride

__global__ __launch_bounds__(256) void flash2_kernel(
    const float* __restrict__ Qh, const float* __restrict__ Kh,
    const float* __restrict__ Vh, const int* __restrict__ kidx,
    const int* __restrict__ kcnt, float* __restrict__ AO)
{
    extern __shared__ float sm[];
    float* Ksm = sm;                    // 64 * LDK
    float* Vsm = Ksm + 64 * LDK;        // 64 * LDV
    float* Psm = Vsm + 64 * LDV;        // 128 * LDQ (Q staging, then per-warp P)

    const int q0 = blockIdx.x * 128;
    const int h  = blockIdx.y;
    const int b  = blockIdx.z;
    const int tid  = threadIdx.x;
    const int lane = tid & 31;
    const int w    = tid >> 5;
    const int g    = lane >> 2;   // group id (row within 8)
    const int t    = lane & 3;    // thread in group
    const int L = kcnt[b];
    const int* idx = kidx + (size_t)b * SS;
    const size_t headbase = (size_t)(b * HH + h) * SS * DKK;
    float* Pw = Psm + w * 16 * LDQ;   // this warp's 16xLDQ region

    // ---- Stage Q tile (pre-scaled, convert to tf32 once) ----
#pragma unroll 2
    for (int i = tid; i < 128 * 16; i += 256) {
        int r = i >> 4, c4 = i & 15;
        float4 v = *(const float4*)&Qh[headbase + (size_t)(q0 + r) * DKK + c4 * 4];
        v.x = f2tf(v.x); v.y = f2tf(v.y); v.z = f2tf(v.z); v.w = f2tf(v.w);
        *(float4*)&Psm[r * LDQ + c4 * 4] = v;
    }
    __syncthreads();

    // ---- Load Q fragments (A layout, m16n8k8): 8 k-steps ----
    uint32_t qa[8][4];
#pragma unroll
    for (int ks = 0; ks < 8; ks++) {
        qa[ks][0] = __float_as_uint(Pw[g * LDQ + ks * 8 + t]);
        qa[ks][1] = __float_as_uint(Pw[(g + 8) * LDQ + ks * 8 + t]);
        qa[ks][2] = __float_as_uint(Pw[g * LDQ + ks * 8 + t + 4]);
        qa[ks][3] = __float_as_uint(Pw[(g + 8) * LDQ + ks * 8 + t + 4]);
    }

    float oacc[8][4];
#pragma unroll
    for (int nt = 0; nt < 8; nt++)
#pragma unroll
        for (int e = 0; e < 4; e++) oacc[nt][e] = 0.0f;
    float m0 = -1e30f, m1 = -1e30f, l0 = 0.0f, l1 = 0.0f;

    const int nkt = (L + 63) >> 6;
    for (int kt = 0; kt < nkt; kt++) {
        const int kbase = kt * 64;
        __syncthreads();   // previous tile's compute done before overwrite

        // ---- Gather K/V tile (zero-fill tail), convert to tf32 ----
#pragma unroll 2
        for (int i = tid; i < 64 * 16; i += 256) {
            int j = i >> 4, c4 = i & 15;
            int gk = kbase + j;
            float4 kv = make_float4(0.f, 0.f, 0.f, 0.f);
            float4 vv = kv;
            if (gk < L) {
                int row = idx[gk];
                kv = *(const float4*)&Kh[headbase + (size_t)row * DKK + c4 * 4];
                vv = *(const float4*)&Vh[headbase + (size_t)row * DKK + c4 * 4];
            }
            kv.x = f2tf(kv.x); kv.y = f2tf(kv.y); kv.z = f2tf(kv.z); kv.w = f2tf(kv.w);
            vv.x = f2tf(vv.x); vv.y = f2tf(vv.y); vv.z = f2tf(vv.z); vv.w = f2tf(vv.w);
            *(float4*)&Ksm[j * LDK + c4 * 4] = kv;
            *(float4*)&Vsm[j * LDV + c4 * 4] = vv;
        }
        __syncthreads();

        // ---- S = Q K^T ----
        float sacc[8][4];
#pragma unroll
        for (int nt = 0; nt < 8; nt++)
#pragma unroll
            for (int e = 0; e < 4; e++) sacc[nt][e] = 0.0f;

#pragma unroll
        for (int ks = 0; ks < 8; ks++) {
#pragma unroll
            for (int nt = 0; nt < 8; nt++) {
                uint32_t b0 = __float_as_uint(Ksm[(nt * 8 + g) * LDK + ks * 8 + t]);
                uint32_t b1 = __float_as_uint(Ksm[(nt * 8 + g) * LDK + ks * 8 + t + 4]);
                mma_tf32(sacc[nt], qa[ks], b0, b1);
            }
        }

        // ---- mask tail columns ----
        if (kbase + 64 > L) {
#pragma unroll
            for (int nt = 0; nt < 8; nt++) {
                int c0 = kbase + nt * 8 + 2 * t;
                if (c0 >= L)     { sacc[nt][0] = -1e30f; sacc[nt][2] = -1e30f; }
                if (c0 + 1 >= L) { sacc[nt][1] = -1e30f; sacc[nt][3] = -1e30f; }
            }
        }

        // ---- online softmax (log2 domain) ----
        float tm0 = -1e30f, tm1 = -1e30f;
#pragma unroll
        for (int nt = 0; nt < 8; nt++) {
            tm0 = fmaxf(tm0, fmaxf(sacc[nt][0], sacc[nt][1]));
            tm1 = fmaxf(tm1, fmaxf(sacc[nt][2], sacc[nt][3]));
        }
        tm0 = fmaxf(tm0, __shfl_xor_sync(0xffffffffu, tm0, 1));
        tm0 = fmaxf(tm0, __shfl_xor_sync(0xffffffffu, tm0, 2));
        tm1 = fmaxf(tm1, __shfl_xor_sync(0xffffffffu, tm1, 1));
        tm1 = fmaxf(tm1, __shfl_xor_sync(0xffffffffu, tm1, 2));

        float mn0 = fmaxf(m0, tm0), mn1 = fmaxf(m1, tm1);
        float al0 = exp2f(m0 - mn0), al1 = exp2f(m1 - mn1);
        float ps0 = 0.f, ps1 = 0.f;
#pragma unroll
        for (int nt = 0; nt < 8; nt++) {
            sacc[nt][0] = exp2f(sacc[nt][0] - mn0);
            sacc[nt][1] = exp2f(sacc[nt][1] - mn0);
            sacc[nt][2] = exp2f(sacc[nt][2] - mn1);
            sacc[nt][3] = exp2f(sacc[nt][3] - mn1);
            ps0 += sacc[nt][0] + sacc[nt][1];
            ps1 += sacc[nt][2] + sacc[nt][3];
        }
        ps0 += __shfl_xor_sync(0xffffffffu, ps0, 1);
        ps0 += __shfl_xor_sync(0xffffffffu, ps0, 2);
        ps1 += __shfl_xor_sync(0xffffffffu, ps1, 1);
        ps1 += __shfl_xor_sync(0xffffffffu, ps1, 2);
        l0 = l0 * al0 + ps0;  m0 = mn0;
        l1 = l1 * al1 + ps1;  m1 = mn1;

#pragma unroll
        for (int nt = 0; nt < 8; nt++) {
            oacc[nt][0] *= al0; oacc[nt][1] *= al0;
            oacc[nt][2] *= al1; oacc[nt][3] *= al1;
        }

        // ---- P C-layout -> warp-private shared (as tf32) ----
#pragma unroll
        for (int nt = 0; nt < 8; nt++) {
            float2 p01 = make_float2(f2tf(sacc[nt][0]), f2tf(sacc[nt][1]));
            float2 p23 = make_float2(f2tf(sacc[nt][2]), f2tf(sacc[nt][3]));
            *(float2*)&Pw[g * LDQ + nt * 8 + 2 * t] = p01;
            *(float2*)&Pw[(g + 8) * LDQ + nt * 8 + 2 * t] = p23;
        }
        __syncwarp();

        // ---- O += P V ----
#pragma unroll
        for (int ks = 0; ks < 8; ks++) {
            uint32_t pa[4];
            pa[0] = __float_as_uint(Pw[g * LDQ + ks * 8 + t]);
            pa[1] = __float_as_uint(Pw[(g + 8) * LDQ + ks * 8 + t]);
            pa[2] = __float_as_uint(Pw[g * LDQ + ks * 8 + t + 4]);
            pa[3] = __float_as_uint(Pw[(g + 8) * LDQ + ks * 8 + t + 4]);
#pragma unroll
            for (int nt = 0; nt < 8; nt++) {
                uint32_t b0 = __float_as_uint(Vsm[(ks * 8 + t) * LDV + nt * 8 + g]);
                uint32_t b1 = __float_as_uint(Vsm[(ks * 8 + t + 4) * LDV + nt * 8 + g]);
                mma_tf32(oacc[nt], pa, b0, b1);
            }
        }
        __syncwarp();   // P reads done before next iteration's P writes
    }

    // ---- Epilogue: normalize, store to AO [b][s][h*64+dk] ----
    float inv0 = (l0 > 0.f) ? (1.0f / l0) : 0.0f;
    float inv1 = (l1 > 0.f) ? (1.0f / l1) : 0.0f;
    int qr0 = q0 + w * 16 + g;
    size_t base0 = ((size_t)b * SS + qr0) * DD + h * DKK;
    size_t base1 = base0 + (size_t)8 * DD;
#pragma unroll
    for (int nt = 0; nt < 8; nt++) {
        *(float2*)&AO[base0 + nt * 8 + 2 * t] =
            make_float2(oacc[nt][0] * inv0, oacc[nt][1] * inv0);
        *(float2*)&AO[base1 + nt * 8 + 2 * t] =
            make_float2(oacc[nt][2] * inv1, oacc[nt][3] * inv1);
    }
}

// ---------------------------------------------------------------------------
// Launch
// ---------------------------------------------------------------------------
extern "C" void kernel_launch(void* const* d_in, const int* in_sizes, int n_in,
                              void* d_out, int out_size)
{
    const float* q    = (const float*)d_in[0];
    const float* k    = (const float*)d_in[1];
    const float* v    = (const float*)d_in[2];
    const int*   mask = (const int*)d_in[3];
    const float* Wq   = (const float*)d_in[4];
    const float* Wk   = (const float*)d_in[5];
    const float* Wv   = (const float*)d_in[6];
    const float* Wo   = (const float*)d_in[7];
    float* out = (float*)d_out;

    float *Qh, *Kh, *Vh, *AO;
    int *kidx, *kcnt;
    cudaGetSymbolAddress((void**)&Qh, g_Qh);
    cudaGetSymbolAddress((void**)&Kh, g_Kh);
    cudaGetSymbolAddress((void**)&Vh, g_Vh);
    cudaGetSymbolAddress((void**)&AO, g_AO);
    cudaGetSymbolAddress((void**)&kidx, g_kidx);
    cudaGetSymbolAddress((void**)&kcnt, g_kcnt);

    const int gsmem = 2 * G_STAGE * (int)sizeof(float);   // 73,728 B
    cudaFuncSetAttribute(gemm2_kernel<true, true>,
                         cudaFuncAttributeMaxDynamicSharedMemorySize, gsmem);
    cudaFuncSetAttribute(gemm2_kernel<true, false>,
                         cudaFuncAttributeMaxDynamicSharedMemorySize, gsmem);
    cudaFuncSetAttribute(gemm2_kernel<false, false>,
                         cudaFuncAttributeMaxDynamicSharedMemorySize, gsmem);

    const int fsmem = (64 * LDK + 64 * LDV + 128 * LDQ) * (int)sizeof(float);
    cudaFuncSetAttribute(flash2_kernel,
                         cudaFuncAttributeMaxDynamicSharedMemorySize, fsmem);

    compact_mask_kernel<<<BB, 32>>>(mask);

    dim3 gproj(MTOT / G_BM, DD / G_BN);   // (64, 4)
    gemm2_kernel<true, true ><<<gproj, 256, gsmem>>>(q, Wq, Qh);
    gemm2_kernel<true, false><<<gproj, 256, gsmem>>>(k, Wk, Kh);
    gemm2_kernel<true, false><<<gproj, 256, gsmem>>>(v, Wv, Vh);

    dim3 gflash(SS / 128, HH, BB);
    flash2_kernel<<<gflash, 256, fsmem>>>(Qh, Kh, Vh,
                                          (const int*)kidx, (const int*)kcnt, AO);

    gemm2_kernel<false, false><<<gproj, 256, gsmem>>>(AO, Wo, out);
}